// round 1
// baseline (speedup 1.0000x reference)
#include <cuda_runtime.h>
#include <cuda_bf16.h>

// Problem constants
#define B_   256
#define IN_  256
#define H_   256
#define L_   2
#define S_   128
#define GATES 1024           // 4*H
#define ROWLEN 512           // H*L floats per (s,b) stack row
#define STACK_ELEMS ((S_ + 1) * B_ * H_ * L_)   // 16,908,288

// ---------------- scratch (device globals; no allocation allowed) ------------
__device__ float g_hp0[B_ * H_];
__device__ float g_hp1[B_ * H_];
__device__ float g_cp0[B_ * H_];
__device__ float g_cp1[B_ * H_];
__device__ float g_G  [B_ * GATES];
__device__ float g_h0 [B_ * H_];
__device__ float g_newh[B_ * ROWLEN];   // (b, h, l) layout — matches a stack row
__device__ float g_newc[B_ * ROWLEN];

// ---------------- gather previous top-of-stack state -------------------------
__global__ void gather_prev(const float* __restrict__ hid,
                            const float* __restrict__ cell,
                            const int* __restrict__ pos,
                            float* __restrict__ hp0, float* __restrict__ hp1,
                            float* __restrict__ cp0, float* __restrict__ cp1) {
    int b = blockIdx.x;
    int h = threadIdx.x;
    int row = (pos[b] * B_ + b) * ROWLEN;
    float2 hv = *(const float2*)(hid  + row + h * 2);
    float2 cv = *(const float2*)(cell + row + h * 2);
    hp0[b * H_ + h] = hv.x;
    hp1[b * H_ + h] = hv.y;
    cp0[b * H_ + h] = cv.x;
    cp1[b * H_ + h] = cv.y;
}

// ---------------- fused dual-GEMM for the 4H gate pre-activations -------------
// G[r][c] = sum_k A1[r][k]*W1[c][k] + sum_k A2[r][k]*W2[c][k] + b1[c] + b2[c]
// A1,A2: (256,256) row-major.  W1,W2: (1024,256) row-major.  G: (256,1024).
#define BM 32
#define BN 64
#define BK 32

__global__ __launch_bounds__(256) void gemm_gates(
    const float* __restrict__ A1, const float* __restrict__ W1,
    const float* __restrict__ A2, const float* __restrict__ W2,
    const float* __restrict__ bias1, const float* __restrict__ bias2,
    float* __restrict__ G)
{
    __shared__ __align__(16) float Ast[BK][BM + 4];  // [k][r]
    __shared__ __align__(16) float Ws [BK][BN + 4];  // [k][c]

    const int tid = threadIdx.x;
    const int c0  = blockIdx.x * BN;
    const int r0  = blockIdx.y * BM;
    const int cg  = tid & 15;    // cols cg*4 .. cg*4+3
    const int rg  = tid >> 4;    // rows rg*2, rg*2+1
    const int kl  = tid & 31;    // k-lane for loads
    const int lw  = tid >> 5;    // 0..7

    float acc[2][4] = {};

    #pragma unroll
    for (int m = 0; m < 2; m++) {
        const float* A = m ? A2 : A1;
        const float* W = m ? W2 : W1;
        for (int kc = 0; kc < 256; kc += BK) {
            #pragma unroll
            for (int i = 0; i < 4; i++) {
                int r = lw + i * 8;
                Ast[kl][r] = A[(r0 + r) * 256 + kc + kl];
            }
            #pragma unroll
            for (int i = 0; i < 8; i++) {
                int c = lw + i * 8;
                Ws[kl][c] = W[(c0 + c) * 256 + kc + kl];
            }
            __syncthreads();
            #pragma unroll
            for (int k = 0; k < BK; k++) {
                float2 a = *(const float2*)&Ast[k][rg * 2];
                float4 w = *(const float4*)&Ws[k][cg * 4];
                acc[0][0] += a.x * w.x; acc[0][1] += a.x * w.y;
                acc[0][2] += a.x * w.z; acc[0][3] += a.x * w.w;
                acc[1][0] += a.y * w.x; acc[1][1] += a.y * w.y;
                acc[1][2] += a.y * w.z; acc[1][3] += a.y * w.w;
            }
            __syncthreads();
        }
    }

    #pragma unroll
    for (int i = 0; i < 2; i++) {
        int r = r0 + rg * 2 + i;
        int c = c0 + cg * 4;
        float4 bsum = make_float4(bias1[c]     + bias2[c],
                                  bias1[c + 1] + bias2[c + 1],
                                  bias1[c + 2] + bias2[c + 2],
                                  bias1[c + 3] + bias2[c + 3]);
        float4 out = make_float4(acc[i][0] + bsum.x, acc[i][1] + bsum.y,
                                 acc[i][2] + bsum.z, acc[i][3] + bsum.w);
        *(float4*)&G[r * GATES + c] = out;
    }
}

// ---------------- LSTM elementwise --------------------------------------------
__device__ __forceinline__ float sigmoidf_(float x) {
    return 1.0f / (1.0f + expf(-x));
}

__global__ void lstm_ew(const float* __restrict__ G,
                        const float* __restrict__ cprev,
                        float* __restrict__ newh, float* __restrict__ newc,
                        float* __restrict__ hdense, int layer) {
    int b = blockIdx.x;
    int h = threadIdx.x;
    const float* g = G + b * GATES;
    float gi = g[h];
    float gf = g[h + 256];
    float gg = g[h + 512];
    float go = g[h + 768];
    float c2 = sigmoidf_(gf) * cprev[b * H_ + h] + sigmoidf_(gi) * tanhf(gg);
    float h2 = sigmoidf_(go) * tanhf(c2);
    newh[b * ROWLEN + h * 2 + layer] = h2;
    newc[b * ROWLEN + h * 2 + layer] = c2;
    if (hdense) hdense[b * H_ + h] = h2;
}

// ---------------- bulk copy + scatter(pos+1) + gather(pos+op) -----------------
// One block per (s,b) stack row; 128 threads, one float4 per thread per stack.
__global__ __launch_bounds__(128) void copy_scatter(
    const float* __restrict__ hid_in, const float* __restrict__ cell_in,
    const float* __restrict__ newh, const float* __restrict__ newc,
    const int* __restrict__ pos, const int* __restrict__ op,
    float* __restrict__ out_h, float* __restrict__ out_c,
    float* __restrict__ out_hid, float* __restrict__ out_cell)
{
    int bid = blockIdx.x;          // = s*256 + b
    int s = bid >> 8;
    int b = bid & 255;
    int t = threadIdx.x;           // 0..127
    int p = __ldg(&pos[b]);
    int row = bid * ROWLEN;

    bool upd = (s == p + 1);
    float4 vh = upd ? ((const float4*)(newh + b * ROWLEN))[t]
                    : ((const float4*)(hid_in + row))[t];
    float4 vc = upd ? ((const float4*)(newc + b * ROWLEN))[t]
                    : ((const float4*)(cell_in + row))[t];

    ((float4*)(out_hid  + row))[t] = vh;
    ((float4*)(out_cell + row))[t] = vc;

    if (t == 127) {
        int np = p + __ldg(&op[b]);
        if (s == np) {
            // last float4 covers (h=254,l=0),(254,1),(255,0),(255,1)
            out_h[b * 2]     = vh.z;
            out_h[b * 2 + 1] = vh.w;
            out_c[b * 2]     = vc.z;
            out_c[b * 2 + 1] = vc.w;
        }
    }
}

// ---------------- launcher ----------------------------------------------------
extern "C" void kernel_launch(void* const* d_in, const int* in_sizes, int n_in,
                              void* d_out, int out_size) {
    const float* x     = (const float*)d_in[0];
    const float* hid   = (const float*)d_in[1];
    const float* cell  = (const float*)d_in[2];
    const float* w_ih0 = (const float*)d_in[3];
    const float* w_hh0 = (const float*)d_in[4];
    const float* b_ih0 = (const float*)d_in[5];
    const float* b_hh0 = (const float*)d_in[6];
    const float* w_ih1 = (const float*)d_in[7];
    const float* w_hh1 = (const float*)d_in[8];
    const float* b_ih1 = (const float*)d_in[9];
    const float* b_hh1 = (const float*)d_in[10];
    const int*   op    = (const int*)d_in[11];
    const int*   pos   = (const int*)d_in[12];

    float* out      = (float*)d_out;
    float* out_h    = out;                       // (1,B,L) = 512
    float* out_c    = out + 512;                 // 512
    float* out_hid  = out + 1024;                // STACK_ELEMS
    float* out_cell = out + 1024 + STACK_ELEMS;  // STACK_ELEMS

    float *hp0, *hp1, *cp0, *cp1, *G, *h0, *newh, *newc;
    cudaGetSymbolAddress((void**)&hp0,  g_hp0);
    cudaGetSymbolAddress((void**)&hp1,  g_hp1);
    cudaGetSymbolAddress((void**)&cp0,  g_cp0);
    cudaGetSymbolAddress((void**)&cp1,  g_cp1);
    cudaGetSymbolAddress((void**)&G,    g_G);
    cudaGetSymbolAddress((void**)&h0,   g_h0);
    cudaGetSymbolAddress((void**)&newh, g_newh);
    cudaGetSymbolAddress((void**)&newc, g_newc);

    // 1. gather previous state at pos
    gather_prev<<<B_, H_>>>(hid, cell, pos, hp0, hp1, cp0, cp1);

    // 2. layer-0 gates
    dim3 ggrid(GATES / BN, B_ / BM);
    gemm_gates<<<ggrid, 256>>>(x, w_ih0, hp0, w_hh0, b_ih0, b_hh0, G);

    // 3. layer-0 elementwise -> h0, c0
    lstm_ew<<<B_, H_>>>(G, cp0, newh, newc, h0, 0);

    // 4. layer-1 gates
    gemm_gates<<<ggrid, 256>>>(h0, w_ih1, hp1, w_hh1, b_ih1, b_hh1, G);

    // 5. layer-1 elementwise -> h1, c1
    lstm_ew<<<B_, H_>>>(G, cp1, newh, newc, nullptr, 1);

    // 6. bulk stack copy with scatter at pos+1 and gather of return state
    copy_scatter<<<(S_ + 1) * B_, 128>>>(hid, cell, newh, newc, pos, op,
                                         out_h, out_c, out_hid, out_cell);
}